// round 15
// baseline (speedup 1.0000x reference)
#include <cuda_runtime.h>
#include <cuda_bf16.h>
#include <cuda_fp16.h>
#include <cstdint>

#define NTH   512                        // edge + node: 16 warps
#define PTH   512
#define ST    136                        // elems per weight-tile row (272 B)
#define TILEB (128 * ST * 2)             // 34816 B per 128x128 16-bit tile
#define YEXB  65536                      // y-exchange: 8mb x 2blk x 8ks x 32lane x 16B
#define EDGE_SMEM (3 * TILEB + YEXB)     // 104448 + 65536 = 169984
#define NODE_SMEM (4 * TILEB)            // U(h,l) V(h,l) bf16 = 139264
#define NODE_PAD 100096

// ---------------- device scratch (static, allowed) ----------------
__device__ __align__(16) __half gVUh[(size_t)NODE_PAD * 128];   // fp16 node projections
__device__ __align__(16) __half gVVh[(size_t)NODE_PAD * 128];
__device__ __align__(16) float gB1p[128];
__device__ __align__(16) char  gWf16[3][TILEB];     // fp16 images: W1a', W1b, W2
__device__ __align__(16) char  gWbf[2][2][TILEB];   // bf16 hi/lo: U_w, V_w (node)

// ---------------- PTX helpers ----------------
__device__ __forceinline__ uint32_t smem_u32(const void* p) {
    uint32_t a;
    asm("{ .reg .u64 t; cvta.to.shared.u64 t, %1; cvt.u32.u64 %0, t; }" : "=r"(a) : "l"(p));
    return a;
}
#define LDSM4(r, addr)                                                              \
    asm volatile("ldmatrix.sync.aligned.m8n8.x4.shared.b16 {%0,%1,%2,%3}, [%4];"    \
                 : "=r"((r)[0]), "=r"((r)[1]), "=r"((r)[2]), "=r"((r)[3])           \
                 : "r"(addr))
__device__ __forceinline__ void mma_bf16(float* c, const uint32_t* a, uint32_t b0, uint32_t b1) {
    asm volatile("mma.sync.aligned.m16n8k16.row.col.f32.bf16.bf16.f32 "
                 "{%0,%1,%2,%3}, {%4,%5,%6,%7}, {%8,%9}, {%0,%1,%2,%3};"
                 : "+f"(c[0]), "+f"(c[1]), "+f"(c[2]), "+f"(c[3])
                 : "r"(a[0]), "r"(a[1]), "r"(a[2]), "r"(a[3]), "r"(b0), "r"(b1));
}
__device__ __forceinline__ void mma_f16(float* c, const uint32_t* a, uint32_t b0, uint32_t b1) {
    asm volatile("mma.sync.aligned.m16n8k16.row.col.f32.f16.f16.f32 "
                 "{%0,%1,%2,%3}, {%4,%5,%6,%7}, {%8,%9}, {%0,%1,%2,%3};"
                 : "+f"(c[0]), "+f"(c[1]), "+f"(c[2]), "+f"(c[3])
                 : "r"(a[0]), "r"(a[1]), "r"(a[2]), "r"(a[3]), "r"(b0), "r"(b1));
}
#define CP16(dst, src) \
    asm volatile("cp.async.ca.shared.global [%0], [%1], 16;" :: "r"(dst), "l"(src))
#define CP_COMMIT() asm volatile("cp.async.commit_group;" ::: "memory")
#define CP_WAIT()   asm volatile("cp.async.wait_group 0;" ::: "memory")

// ---------------- numeric helpers ----------------
__device__ __forceinline__ float bf16hi_rn(float a, uint32_t& hbits) {
    uint32_t u = __float_as_uint(a);
    uint32_t r = (u + 0x7FFFu + ((u >> 16) & 1u)) & 0xFFFF0000u;
    hbits = r;
    return __uint_as_float(r);
}
__device__ __forceinline__ uint32_t bf16x2_of(float lo, float hi) {
    uint32_t r;
    asm("cvt.rn.bf16x2.f32 %0, %1, %2;" : "=r"(r) : "f"(hi), "f"(lo));
    return r;
}
__device__ __forceinline__ uint32_t h2_of(float lo, float hi) {
    uint32_t r;
    asm("cvt.rn.f16x2.f32 %0, %1, %2;" : "=r"(r) : "f"(hi), "f"(lo));
    return r;
}
__device__ __forceinline__ float2 h2tof2(uint32_t v) {
    __half2 h = *reinterpret_cast<__half2*>(&v);
    return __half22float2(h);
}
__device__ __forceinline__ void split2(float x, float y, uint32_t& h, uint32_t& l) {
    uint32_t rx, ry;
    float hx = bf16hi_rn(x, rx), hy = bf16hi_rn(y, ry);
    h = __byte_perm(rx, ry, 0x7632);
    l = bf16x2_of(x - hx, y - hy);
}
__device__ __forceinline__ float fast_tanh(float x) {
    float e = __expf(2.f * x);
    return 1.f - __fdividef(2.f, e + 1.f);
}
__device__ __forceinline__ float lk(float v) { return v > 0.f ? v : 0.01f * v; }

// bf16 hi/lo staging (node weights)
__device__ __forceinline__ void stage32(const float* __restrict__ src,
                                        char* Xh, char* Xl, uint32_t off) {
    #pragma unroll
    for (int i = 0; i < 8; ++i) {
        float4 t = reinterpret_cast<const float4*>(src)[i];
        uint32_t r0, r1, r2, r3;
        float h0 = bf16hi_rn(t.x, r0), h1 = bf16hi_rn(t.y, r1);
        float h2 = bf16hi_rn(t.z, r2), h3 = bf16hi_rn(t.w, r3);
        uint2 hh = make_uint2(__byte_perm(r0, r1, 0x7632), __byte_perm(r2, r3, 0x7632));
        uint2 ll = make_uint2(bf16x2_of(t.x - h0, t.y - h1), bf16x2_of(t.z - h2, t.w - h3));
        *reinterpret_cast<uint2*>(Xh + off + i * 8) = hh;
        *reinterpret_cast<uint2*>(Xl + off + i * 8) = ll;
    }
}
// fp16 single staging (edge weights)
__device__ __forceinline__ void stage32h(const float* __restrict__ src,
                                         char* X, uint32_t off) {
    #pragma unroll
    for (int i = 0; i < 8; ++i) {
        float4 t = reinterpret_cast<const float4*>(src)[i];
        uint2 v = make_uint2(h2_of(t.x, t.y), h2_of(t.z, t.w));
        *reinterpret_cast<uint2*>(X + off + i * 8) = v;
    }
}

// bf16 3-term helper for node kernel
__device__ __forceinline__ void mma6(float* acc, const uint32_t* ah, const uint32_t* al,
                                     const uint32_t* bh, const uint32_t* bl) {
    mma_bf16(acc,     ah, bh[0], bh[1]);
    mma_bf16(acc + 4, ah, bh[2], bh[3]);
    mma_bf16(acc,     ah, bl[0], bl[1]);
    mma_bf16(acc + 4, ah, bl[2], bl[3]);
    mma_bf16(acc,     al, bh[0], bh[1]);
    mma_bf16(acc + 4, al, bh[2], bh[3]);
}
__device__ __forceinline__ void gemm_groups(float* acc, const uint32_t* ah, const uint32_t* al,
                                            uint32_t baseH, uint32_t baseL, int ngroups)
{
    #pragma unroll
    for (int g = 0; g < 8; ++g) {
        if (g >= ngroups) break;
        uint32_t bh[4], bl[4];
        LDSM4(bh, baseH + g * (16 * ST * 2));
        LDSM4(bl, baseL + g * (16 * ST * 2));
        mma6(acc + 8 * g, ah, al, bh, bl);
    }
}

// ================= prep 1: W1a' = W1a @ P_w (emit fp16 image 0), b1' =================
__global__ void __launch_bounds__(128, 1)
ecat_compose(const float* __restrict__ W1, const float* __restrict__ P_w,
             const float* __restrict__ P_b, const float* __restrict__ b1)
{
    __shared__ float srow[128];
    int o = blockIdx.x;
    int j = threadIdx.x;
    srow[j] = W1[o * 256 + j];
    __syncthreads();
    float acc = 0.f;
    #pragma unroll 4
    for (int i = 0; i < 128; ++i)
        acc += srow[i] * P_w[i * 128 + j];
    reinterpret_cast<__half*>(gWf16[0])[o * ST + j] = __float2half_rn(acc);
    if (j == 0) {
        float s = 0.f;
        for (int i = 0; i < 128; ++i) s += srow[i] * P_b[i];
        gB1p[o] = b1[o] + s;
    }
}

// ================= prep 2: W1b, W2 -> fp16; U_w, V_w -> bf16 hi/lo =================
__global__ void __launch_bounds__(PTH, 1)
ecat_convert(const float* __restrict__ W1, const float* __restrict__ W2,
             const float* __restrict__ U_w, const float* __restrict__ V_w)
{
    int b = blockIdx.x;
    int tid = threadIdx.x;
    int o = tid >> 2, qo = (tid & 3) * 32;
    uint32_t off = (uint32_t)(o * ST + qo) * 2;
    if (b == 0)      stage32h(W1 + o * 256 + 128 + qo, (char*)gWf16[1], off);
    else if (b == 1) stage32h(W2 + o * 128 + qo, (char*)gWf16[2], off);
    else if (b == 2) stage32(U_w + (size_t)o * 128 + qo, (char*)gWbf[0][0], (char*)gWbf[0][1], off);
    else             stage32(V_w + (size_t)o * 128 + qo, (char*)gWbf[1][0], (char*)gWbf[1][1], off);
}

// ================= prep 3: VU / VV (bf16 3-term compute, fp16 output) =================
__global__ void __launch_bounds__(NTH, 1)
ecat_node(const float* __restrict__ V, int n_nodes, int n_ntiles)
{
    extern __shared__ char sm[];
    uint32_t smb = smem_u32(sm);
    const char* gsrc = &gWbf[0][0][0];
    #pragma unroll
    for (int i = 0; i < 17; ++i) {
        int idx = i * NTH + threadIdx.x;
        CP16(smb + idx * 16, gsrc + idx * 16);   // 17*512 = 8704 chunks exactly
    }
    CP_COMMIT(); CP_WAIT();
    __syncthreads();

    const int tid = threadIdx.x, lane = tid & 31, w = tid >> 5;
    const int r0 = lane >> 2, il = lane & 3, cb = il * 2;
    const uint32_t offB = (uint32_t)(((lane & 7) + (((lane >> 4) & 1) << 3)) * ST
                                     + (((lane >> 3) & 1) << 3)) * 2;

    for (int t = blockIdx.x; t < n_ntiles; t += gridDim.x) {
        int n0 = t * 256 + w * 16 + r0;
        int n1 = n0 + 8;
        int n0c = n0 < n_nodes ? n0 : 0;
        int n1c = n1 < n_nodes ? n1 : 0;
        const float2* pa0 = reinterpret_cast<const float2*>(V + (size_t)n0c * 128);
        const float2* pa1 = reinterpret_cast<const float2*>(V + (size_t)n1c * 128);

        #pragma unroll 1
        for (int pass = 0; pass < 2; ++pass) {
            uint32_t bH = smb + pass * 2 * TILEB, bL = bH + TILEB;
            float acc[64];
            #pragma unroll
            for (int i = 0; i < 64; ++i) acc[i] = 0.f;
            #pragma unroll 1
            for (int ks = 0; ks < 8; ++ks) {
                int i0 = il + 8 * ks, i1 = i0 + 4;
                float2 a0 = pa0[i0], b0 = pa1[i0], c0 = pa0[i1], d0 = pa1[i1];
                uint32_t ah[4], al[4];
                split2(a0.x, a0.y, ah[0], al[0]);
                split2(b0.x, b0.y, ah[1], al[1]);
                split2(c0.x, c0.y, ah[2], al[2]);
                split2(d0.x, d0.y, ah[3], al[3]);
                gemm_groups(acc, ah, al, bH + offB + ks * 32, bL + offB + ks * 32, 8);
            }
            uint32_t* dstb = reinterpret_cast<uint32_t*>(pass ? gVVh : gVUh);
            #pragma unroll
            for (int nf = 0; nf < 16; ++nf) {
                int cw = nf * 4 + il;     // half2 word index within row (col = nf*8+cb)
                if (n0 < n_nodes)
                    dstb[(size_t)n0 * 64 + cw] = h2_of(acc[nf*4],   acc[nf*4+1]);
                if (n1 < n_nodes)
                    dstb[(size_t)n1 * 64 + cw] = h2_of(acc[nf*4+2], acc[nf*4+3]);
            }
        }
    }
}

// ============ main edge kernel: 8mb x 2h warps, m=32 x n=64, smem y-exchange ============
__global__ void __launch_bounds__(NTH, 1)
ecat_edge(const float* __restrict__ E, const int* __restrict__ src,
          const int* __restrict__ dst, const float* __restrict__ b2,
          float* __restrict__ out, int n_tiles)
{
    extern __shared__ char sm[];
    uint32_t smb = smem_u32(sm);
    const char* gsrc = &gWf16[0][0];
    #pragma unroll
    for (int i = 0; i < 13; ++i) {                 // 3*TILEB/16 = 6528 chunks
        int idx = i * NTH + threadIdx.x;
        if (idx < 3 * TILEB / 16) CP16(smb + idx * 16, gsrc + idx * 16);
    }
    CP_COMMIT(); CP_WAIT();
    __syncthreads();

    uint4* ySm = reinterpret_cast<uint4*>(sm + 3 * TILEB);   // [mb*2+blk][ks][lane]

    const int tid = threadIdx.x, lane = tid & 31, w = tid >> 5;
    const int mb = w & 7, h = w >> 3;
    const int r0 = lane >> 2, il = lane & 3, cb = il * 2;
    const uint32_t nBase = (uint32_t)h * (64 * ST * 2);
    const uint32_t offB = (uint32_t)(((lane & 7) + (((lane >> 4) & 1) << 3)) * ST
                                     + (((lane >> 3) & 1) << 3)) * 2;
    const uint32_t uW1a = smb, uW1b = smb + TILEB, uW2 = smb + 2 * TILEB;
    const uint32_t* gVUp = reinterpret_cast<const uint32_t*>(gVUh);
    const uint32_t* gVVp = reinterpret_cast<const uint32_t*>(gVVh);

    for (int t = blockIdx.x; t < n_tiles; t += gridDim.x) {
        long eb = (long)t * 256 + mb * 32 + r0;    // warp rows: eb + 8q, q=0..3
        const uint32_t* pu[4];
        const uint32_t* pv[4];
        #pragma unroll
        for (int q = 0; q < 4; ++q) {
            long er = eb + q * 8;
            pu[q] = gVUp + (size_t)__ldg(src + er) * 64;
            pv[q] = gVVp + (size_t)__ldg(dst + er) * 64;
        }
        const float2* pe = reinterpret_cast<const float2*>(E + eb * 128);  // row q at +512q

        float acc0[32], acc1[32];
        #pragma unroll
        for (int i = 0; i < 32; ++i) { acc0[i] = 0.f; acc1[i] = 0.f; }

        // ---- merged GEMM A+B over this warp's n-half; B shared by both m-blocks ----
        #pragma unroll 1
        for (int ks = 0; ks < 8; ++ks) {
            int i0 = il + 8 * ks, i1 = i0 + 4;
            uint32_t th0[4], th1[4], eh0[4], eh1[4];
            {   // m-block 0: rows q0, q1
                float2 u0 = h2tof2(pu[0][i0]), u1 = h2tof2(pu[1][i0]);
                float2 u2 = h2tof2(pu[0][i1]), u3 = h2tof2(pu[1][i1]);
                float2 v0 = h2tof2(pv[0][i0]), v1 = h2tof2(pv[1][i0]);
                float2 v2 = h2tof2(pv[0][i1]), v3 = h2tof2(pv[1][i1]);
                th0[0] = h2_of(fast_tanh(u0.x * v0.x), fast_tanh(u0.y * v0.y));
                th0[1] = h2_of(fast_tanh(u1.x * v1.x), fast_tanh(u1.y * v1.y));
                th0[2] = h2_of(fast_tanh(u2.x * v2.x), fast_tanh(u2.y * v2.y));
                th0[3] = h2_of(fast_tanh(u3.x * v3.x), fast_tanh(u3.y * v3.y));
            }
            {   // m-block 1: rows q2, q3
                float2 u0 = h2tof2(pu[2][i0]), u1 = h2tof2(pu[3][i0]);
                float2 u2 = h2tof2(pu[2][i1]), u3 = h2tof2(pu[3][i1]);
                float2 v0 = h2tof2(pv[2][i0]), v1 = h2tof2(pv[3][i0]);
                float2 v2 = h2tof2(pv[2][i1]), v3 = h2tof2(pv[3][i1]);
                th1[0] = h2_of(fast_tanh(u0.x * v0.x), fast_tanh(u0.y * v0.y));
                th1[1] = h2_of(fast_tanh(u1.x * v1.x), fast_tanh(u1.y * v1.y));
                th1[2] = h2_of(fast_tanh(u2.x * v2.x), fast_tanh(u2.y * v2.y));
                th1[3] = h2_of(fast_tanh(u3.x * v3.x), fast_tanh(u3.y * v3.y));
            }
            {
                float2 e0 = pe[i0],        e1 = pe[512 + i0];
                float2 e2 = pe[i1],        e3 = pe[512 + i1];
                eh0[0] = h2_of(lk(e0.x), lk(e0.y));
                eh0[1] = h2_of(lk(e1.x), lk(e1.y));
                eh0[2] = h2_of(lk(e2.x), lk(e2.y));
                eh0[3] = h2_of(lk(e3.x), lk(e3.y));
                float2 f0 = pe[1024 + i0], f1 = pe[1536 + i0];
                float2 f2 = pe[1024 + i1], f3 = pe[1536 + i1];
                eh1[0] = h2_of(lk(f0.x), lk(f0.y));
                eh1[1] = h2_of(lk(f1.x), lk(f1.y));
                eh1[2] = h2_of(lk(f2.x), lk(f2.y));
                eh1[3] = h2_of(lk(f3.x), lk(f3.y));
            }
            const uint32_t bA = uW1a + nBase + offB + ks * 32;
            const uint32_t bB = uW1b + nBase + offB + ks * 32;
            #pragma unroll
            for (int g = 0; g < 4; ++g) {
                uint32_t go = (uint32_t)g * (16 * ST * 2);
                uint32_t ba[4], bb[4];
                LDSM4(ba, bA + go);
                LDSM4(bb, bB + go);
                mma_f16(acc0 + 8 * g,     th0, ba[0], ba[1]);
                mma_f16(acc0 + 8 * g + 4, th0, ba[2], ba[3]);
                mma_f16(acc1 + 8 * g,     th1, ba[0], ba[1]);
                mma_f16(acc1 + 8 * g + 4, th1, ba[2], ba[3]);
                mma_f16(acc0 + 8 * g,     eh0, bb[0], bb[1]);
                mma_f16(acc0 + 8 * g + 4, eh0, bb[2], bb[3]);
                mma_f16(acc1 + 8 * g,     eh1, bb[0], bb[1]);
                mma_f16(acc1 + 8 * g + 4, eh1, bb[2], bb[3]);
            }
        }

        // ---- y1 = relu(acc + b1') -> fp16 frags -> smem exchange ----
        #pragma unroll
        for (int kl = 0; kl < 4; ++kl) {
            int n0f = 2 * kl, n1f = 2 * kl + 1;
            float2 bb0 = __ldg(reinterpret_cast<const float2*>(gB1p + h * 64 + n0f * 8 + cb));
            float2 bb1 = __ldg(reinterpret_cast<const float2*>(gB1p + h * 64 + n1f * 8 + cb));
            uint4 Y;
            Y.x = h2_of(fmaxf(acc0[n0f*4+0] + bb0.x, 0.f), fmaxf(acc0[n0f*4+1] + bb0.y, 0.f));
            Y.y = h2_of(fmaxf(acc0[n0f*4+2] + bb0.x, 0.f), fmaxf(acc0[n0f*4+3] + bb0.y, 0.f));
            Y.z = h2_of(fmaxf(acc0[n1f*4+0] + bb1.x, 0.f), fmaxf(acc0[n1f*4+1] + bb1.y, 0.f));
            Y.w = h2_of(fmaxf(acc0[n1f*4+2] + bb1.x, 0.f), fmaxf(acc0[n1f*4+3] + bb1.y, 0.f));
            ySm[((mb * 2 + 0) * 8 + 4 * h + kl) * 32 + lane] = Y;
            Y.x = h2_of(fmaxf(acc1[n0f*4+0] + bb0.x, 0.f), fmaxf(acc1[n0f*4+1] + bb0.y, 0.f));
            Y.y = h2_of(fmaxf(acc1[n0f*4+2] + bb0.x, 0.f), fmaxf(acc1[n0f*4+3] + bb0.y, 0.f));
            Y.z = h2_of(fmaxf(acc1[n1f*4+0] + bb1.x, 0.f), fmaxf(acc1[n1f*4+1] + bb1.y, 0.f));
            Y.w = h2_of(fmaxf(acc1[n1f*4+2] + bb1.x, 0.f), fmaxf(acc1[n1f*4+3] + bb1.y, 0.f));
            ySm[((mb * 2 + 1) * 8 + 4 * h + kl) * 32 + lane] = Y;
        }
        __syncthreads();   // all y-frags of the tile visible

        // ---- GEMM C: full k from exchange, this warp's n-half, B shared by m-blocks ----
        float c0[32], c1[32];
        #pragma unroll
        for (int i = 0; i < 32; ++i) { c0[i] = 0.f; c1[i] = 0.f; }
        #pragma unroll 1
        for (int ks = 0; ks < 8; ++ks) {
            uint4 Y0 = ySm[((mb * 2 + 0) * 8 + ks) * 32 + lane];
            uint4 Y1 = ySm[((mb * 2 + 1) * 8 + ks) * 32 + lane];
            uint32_t y0[4] = {Y0.x, Y0.y, Y0.z, Y0.w};
            uint32_t y1[4] = {Y1.x, Y1.y, Y1.z, Y1.w};
            const uint32_t bC = uW2 + nBase + offB + ks * 32;
            #pragma unroll
            for (int g = 0; g < 4; ++g) {
                uint32_t go = (uint32_t)g * (16 * ST * 2);
                uint32_t bc[4];
                LDSM4(bc, bC + go);
                mma_f16(c0 + 8 * g,     y0, bc[0], bc[1]);
                mma_f16(c0 + 8 * g + 4, y0, bc[2], bc[3]);
                mma_f16(c1 + 8 * g,     y1, bc[0], bc[1]);
                mma_f16(c1 + 8 * g + 4, y1, bc[2], bc[3]);
            }
        }
        #pragma unroll
        for (int nf = 0; nf < 8; ++nf) {
            int c = h * 64 + nf * 8 + cb;
            float2 bb = __ldg(reinterpret_cast<const float2*>(b2 + c));
            *reinterpret_cast<float2*>(out + (eb)      * 128 + c) =
                make_float2(fmaxf(c0[nf*4+0] + bb.x, 0.f), fmaxf(c0[nf*4+1] + bb.y, 0.f));
            *reinterpret_cast<float2*>(out + (eb + 8)  * 128 + c) =
                make_float2(fmaxf(c0[nf*4+2] + bb.x, 0.f), fmaxf(c0[nf*4+3] + bb.y, 0.f));
            *reinterpret_cast<float2*>(out + (eb + 16) * 128 + c) =
                make_float2(fmaxf(c1[nf*4+0] + bb.x, 0.f), fmaxf(c1[nf*4+1] + bb.y, 0.f));
            *reinterpret_cast<float2*>(out + (eb + 24) * 128 + c) =
                make_float2(fmaxf(c1[nf*4+2] + bb.x, 0.f), fmaxf(c1[nf*4+3] + bb.y, 0.f));
        }
        __syncthreads();   // protect ySm before next tile overwrites
    }
}

// ================= host =================
extern "C" void kernel_launch(void* const* d_in, const int* in_sizes, int n_in,
                              void* d_out, int out_size)
{
    const float* V   = (const float*)d_in[0];
    const float* E   = (const float*)d_in[1];
    const int*   src = (const int*)d_in[2];
    const int*   dst = (const int*)d_in[3];
    const float* U_w = (const float*)d_in[4];
    const float* V_w = (const float*)d_in[5];
    const float* P_w = (const float*)d_in[6];
    const float* P_b = (const float*)d_in[7];
    const float* W1  = (const float*)d_in[8];
    const float* b1  = (const float*)d_in[9];
    const float* W2  = (const float*)d_in[10];
    const float* b2  = (const float*)d_in[11];
    float* out = (float*)d_out;

    int n_nodes = in_sizes[0] / 128;
    int n_edges = in_sizes[2];
    int n_tiles = n_edges / 256;                 // 2500
    int n_ntiles = (n_nodes + 255) / 256;        // 391

    static int sms = 0;
    if (!sms) {
        cudaDeviceGetAttribute(&sms, cudaDevAttrMultiProcessorCount, 0);
        cudaFuncSetAttribute(ecat_node, cudaFuncAttributeMaxDynamicSharedMemorySize, NODE_SMEM);
        cudaFuncSetAttribute(ecat_edge, cudaFuncAttributeMaxDynamicSharedMemorySize, EDGE_SMEM);
    }

    ecat_compose<<<128, 128>>>(W1, P_w, P_b, b1);
    ecat_convert<<<4, PTH>>>(W1, W2, U_w, V_w);
    ecat_node<<<sms, NTH, NODE_SMEM>>>(V, n_nodes, n_ntiles);
    ecat_edge<<<sms, NTH, EDGE_SMEM>>>(E, src, dst, b2, out, n_tiles);
}

// round 16
// speedup vs baseline: 1.2526x; 1.2526x over previous
#include <cuda_runtime.h>
#include <cuda_bf16.h>
#include <cuda_fp16.h>
#include <cstdint>

#define NTH   512                        // edge + node: 16 warps, m=16 per warp
#define PTH   512
#define ST    136                        // elems per weight-tile row (272 B)
#define TILEB (128 * ST * 2)             // 34816 B per 128x128 16-bit tile
#define EDGE_SMEM (3 * TILEB)            // W1a' W1b W2 fp16 = 104448
#define NODE_SMEM (4 * TILEB)            // U(h,l) V(h,l) bf16 = 139264
#define NODE_PAD 100096

// ---------------- device scratch (static, allowed) ----------------
__device__ __align__(16) __half gVUh[(size_t)NODE_PAD * 128];   // fp16 node projections
__device__ __align__(16) __half gVVh[(size_t)NODE_PAD * 128];
__device__ __align__(16) float gB1p[128];
__device__ __align__(16) char  gWf16[3][TILEB];     // fp16 images: W1a', W1b, W2
__device__ __align__(16) char  gWbf[2][2][TILEB];   // bf16 hi/lo: U_w, V_w (node)

// ---------------- PTX helpers ----------------
__device__ __forceinline__ uint32_t smem_u32(const void* p) {
    uint32_t a;
    asm("{ .reg .u64 t; cvta.to.shared.u64 t, %1; cvt.u32.u64 %0, t; }" : "=r"(a) : "l"(p));
    return a;
}
#define LDSM4(r, addr)                                                              \
    asm volatile("ldmatrix.sync.aligned.m8n8.x4.shared.b16 {%0,%1,%2,%3}, [%4];"    \
                 : "=r"((r)[0]), "=r"((r)[1]), "=r"((r)[2]), "=r"((r)[3])           \
                 : "r"(addr))
__device__ __forceinline__ void mma_bf16(float* c, const uint32_t* a, uint32_t b0, uint32_t b1) {
    asm volatile("mma.sync.aligned.m16n8k16.row.col.f32.bf16.bf16.f32 "
                 "{%0,%1,%2,%3}, {%4,%5,%6,%7}, {%8,%9}, {%0,%1,%2,%3};"
                 : "+f"(c[0]), "+f"(c[1]), "+f"(c[2]), "+f"(c[3])
                 : "r"(a[0]), "r"(a[1]), "r"(a[2]), "r"(a[3]), "r"(b0), "r"(b1));
}
__device__ __forceinline__ void mma_f16(float* c, const uint32_t* a, uint32_t b0, uint32_t b1) {
    asm volatile("mma.sync.aligned.m16n8k16.row.col.f32.f16.f16.f32 "
                 "{%0,%1,%2,%3}, {%4,%5,%6,%7}, {%8,%9}, {%0,%1,%2,%3};"
                 : "+f"(c[0]), "+f"(c[1]), "+f"(c[2]), "+f"(c[3])
                 : "r"(a[0]), "r"(a[1]), "r"(a[2]), "r"(a[3]), "r"(b0), "r"(b1));
}
#define CP16(dst, src) \
    asm volatile("cp.async.ca.shared.global [%0], [%1], 16;" :: "r"(dst), "l"(src))
#define CP_COMMIT() asm volatile("cp.async.commit_group;" ::: "memory")
#define CP_WAIT()   asm volatile("cp.async.wait_group 0;" ::: "memory")

// ---------------- numeric helpers ----------------
__device__ __forceinline__ float bf16hi_rn(float a, uint32_t& hbits) {
    uint32_t u = __float_as_uint(a);
    uint32_t r = (u + 0x7FFFu + ((u >> 16) & 1u)) & 0xFFFF0000u;
    hbits = r;
    return __uint_as_float(r);
}
__device__ __forceinline__ uint32_t bf16x2_of(float lo, float hi) {
    uint32_t r;
    asm("cvt.rn.bf16x2.f32 %0, %1, %2;" : "=r"(r) : "f"(hi), "f"(lo));
    return r;
}
__device__ __forceinline__ uint32_t h2_of(float lo, float hi) {
    uint32_t r;
    asm("cvt.rn.f16x2.f32 %0, %1, %2;" : "=r"(r) : "f"(hi), "f"(lo));
    return r;
}
__device__ __forceinline__ float2 h2tof2(uint32_t v) {
    __half2 h = *reinterpret_cast<__half2*>(&v);
    return __half22float2(h);
}
__device__ __forceinline__ void split2(float x, float y, uint32_t& h, uint32_t& l) {
    uint32_t rx, ry;
    float hx = bf16hi_rn(x, rx), hy = bf16hi_rn(y, ry);
    h = __byte_perm(rx, ry, 0x7632);
    l = bf16x2_of(x - hx, y - hy);
}
__device__ __forceinline__ float fast_tanh(float x) {
    float e = __expf(2.f * x);
    return 1.f - __fdividef(2.f, e + 1.f);
}
__device__ __forceinline__ float lk(float v) { return v > 0.f ? v : 0.01f * v; }

// bf16 hi/lo staging (node weights)
__device__ __forceinline__ void stage32(const float* __restrict__ src,
                                        char* Xh, char* Xl, uint32_t off) {
    #pragma unroll
    for (int i = 0; i < 8; ++i) {
        float4 t = reinterpret_cast<const float4*>(src)[i];
        uint32_t r0, r1, r2, r3;
        float h0 = bf16hi_rn(t.x, r0), h1 = bf16hi_rn(t.y, r1);
        float h2 = bf16hi_rn(t.z, r2), h3 = bf16hi_rn(t.w, r3);
        uint2 hh = make_uint2(__byte_perm(r0, r1, 0x7632), __byte_perm(r2, r3, 0x7632));
        uint2 ll = make_uint2(bf16x2_of(t.x - h0, t.y - h1), bf16x2_of(t.z - h2, t.w - h3));
        *reinterpret_cast<uint2*>(Xh + off + i * 8) = hh;
        *reinterpret_cast<uint2*>(Xl + off + i * 8) = ll;
    }
}
// fp16 single staging (edge weights)
__device__ __forceinline__ void stage32h(const float* __restrict__ src,
                                         char* X, uint32_t off) {
    #pragma unroll
    for (int i = 0; i < 8; ++i) {
        float4 t = reinterpret_cast<const float4*>(src)[i];
        uint2 v = make_uint2(h2_of(t.x, t.y), h2_of(t.z, t.w));
        *reinterpret_cast<uint2*>(X + off + i * 8) = v;
    }
}

// bf16 3-term helper for node kernel
__device__ __forceinline__ void mma6(float* acc, const uint32_t* ah, const uint32_t* al,
                                     const uint32_t* bh, const uint32_t* bl) {
    mma_bf16(acc,     ah, bh[0], bh[1]);
    mma_bf16(acc + 4, ah, bh[2], bh[3]);
    mma_bf16(acc,     ah, bl[0], bl[1]);
    mma_bf16(acc + 4, ah, bl[2], bl[3]);
    mma_bf16(acc,     al, bh[0], bh[1]);
    mma_bf16(acc + 4, al, bh[2], bh[3]);
}
__device__ __forceinline__ void gemm_groups(float* acc, const uint32_t* ah, const uint32_t* al,
                                            uint32_t baseH, uint32_t baseL, int ngroups)
{
    #pragma unroll
    for (int g = 0; g < 8; ++g) {
        if (g >= ngroups) break;
        uint32_t bh[4], bl[4];
        LDSM4(bh, baseH + g * (16 * ST * 2));
        LDSM4(bl, baseL + g * (16 * ST * 2));
        mma6(acc + 8 * g, ah, al, bh, bl);
    }
}

// ================= prep 1: W1a' = W1a @ P_w (emit fp16 image 0), b1' =================
__global__ void __launch_bounds__(128, 1)
ecat_compose(const float* __restrict__ W1, const float* __restrict__ P_w,
             const float* __restrict__ P_b, const float* __restrict__ b1)
{
    __shared__ float srow[128];
    int o = blockIdx.x;
    int j = threadIdx.x;
    srow[j] = W1[o * 256 + j];
    __syncthreads();
    float acc = 0.f;
    #pragma unroll 4
    for (int i = 0; i < 128; ++i)
        acc += srow[i] * P_w[i * 128 + j];
    reinterpret_cast<__half*>(gWf16[0])[o * ST + j] = __float2half_rn(acc);
    if (j == 0) {
        float s = 0.f;
        for (int i = 0; i < 128; ++i) s += srow[i] * P_b[i];
        gB1p[o] = b1[o] + s;
    }
}

// ================= prep 2: W1b, W2 -> fp16; U_w, V_w -> bf16 hi/lo =================
__global__ void __launch_bounds__(PTH, 1)
ecat_convert(const float* __restrict__ W1, const float* __restrict__ W2,
             const float* __restrict__ U_w, const float* __restrict__ V_w)
{
    int b = blockIdx.x;
    int tid = threadIdx.x;
    int o = tid >> 2, qo = (tid & 3) * 32;
    uint32_t off = (uint32_t)(o * ST + qo) * 2;
    if (b == 0)      stage32h(W1 + o * 256 + 128 + qo, (char*)gWf16[1], off);
    else if (b == 1) stage32h(W2 + o * 128 + qo, (char*)gWf16[2], off);
    else if (b == 2) stage32(U_w + (size_t)o * 128 + qo, (char*)gWbf[0][0], (char*)gWbf[0][1], off);
    else             stage32(V_w + (size_t)o * 128 + qo, (char*)gWbf[1][0], (char*)gWbf[1][1], off);
}

// ================= prep 3: VU / VV (bf16 3-term compute, fp16 output) =================
__global__ void __launch_bounds__(NTH, 1)
ecat_node(const float* __restrict__ V, int n_nodes, int n_ntiles)
{
    extern __shared__ char sm[];
    uint32_t smb = smem_u32(sm);
    const char* gsrc = &gWbf[0][0][0];
    #pragma unroll
    for (int i = 0; i < 17; ++i) {
        int idx = i * NTH + threadIdx.x;
        CP16(smb + idx * 16, gsrc + idx * 16);   // 17*512 = 8704 chunks exactly
    }
    CP_COMMIT(); CP_WAIT();
    __syncthreads();

    const int tid = threadIdx.x, lane = tid & 31, w = tid >> 5;
    const int r0 = lane >> 2, il = lane & 3, cb = il * 2;
    const uint32_t offB = (uint32_t)(((lane & 7) + (((lane >> 4) & 1) << 3)) * ST
                                     + (((lane >> 3) & 1) << 3)) * 2;

    for (int t = blockIdx.x; t < n_ntiles; t += gridDim.x) {
        int n0 = t * 256 + w * 16 + r0;
        int n1 = n0 + 8;
        int n0c = n0 < n_nodes ? n0 : 0;
        int n1c = n1 < n_nodes ? n1 : 0;
        const float2* pa0 = reinterpret_cast<const float2*>(V + (size_t)n0c * 128);
        const float2* pa1 = reinterpret_cast<const float2*>(V + (size_t)n1c * 128);

        #pragma unroll 1
        for (int pass = 0; pass < 2; ++pass) {
            uint32_t bH = smb + pass * 2 * TILEB, bL = bH + TILEB;
            float acc[64];
            #pragma unroll
            for (int i = 0; i < 64; ++i) acc[i] = 0.f;
            #pragma unroll 1
            for (int ks = 0; ks < 8; ++ks) {
                int i0 = il + 8 * ks, i1 = i0 + 4;
                float2 a0 = pa0[i0], b0 = pa1[i0], c0 = pa0[i1], d0 = pa1[i1];
                uint32_t ah[4], al[4];
                split2(a0.x, a0.y, ah[0], al[0]);
                split2(b0.x, b0.y, ah[1], al[1]);
                split2(c0.x, c0.y, ah[2], al[2]);
                split2(d0.x, d0.y, ah[3], al[3]);
                gemm_groups(acc, ah, al, bH + offB + ks * 32, bL + offB + ks * 32, 8);
            }
            uint32_t* dstb = reinterpret_cast<uint32_t*>(pass ? gVVh : gVUh);
            #pragma unroll
            for (int nf = 0; nf < 16; ++nf) {
                int cw = nf * 4 + il;     // half2 word index within row (col = nf*8+cb)
                if (n0 < n_nodes)
                    dstb[(size_t)n0 * 64 + cw] = h2_of(acc[nf*4],   acc[nf*4+1]);
                if (n1 < n_nodes)
                    dstb[(size_t)n1 * 64 + cw] = h2_of(acc[nf*4+2], acc[nf*4+3]);
            }
        }
    }
}

// ========== main edge kernel: R13 structure (m=16, full n), fp16 gathers ==========
__global__ void __launch_bounds__(NTH, 1)
ecat_edge(const float* __restrict__ E, const int* __restrict__ src,
          const int* __restrict__ dst, const float* __restrict__ b2,
          float* __restrict__ out, int n_tiles)
{
    extern __shared__ char sm[];
    uint32_t smb = smem_u32(sm);
    const char* gsrc = &gWf16[0][0];
    #pragma unroll
    for (int i = 0; i < 13; ++i) {                 // 3*TILEB/16 = 6528 chunks
        int idx = i * NTH + threadIdx.x;
        if (idx < 3 * TILEB / 16) CP16(smb + idx * 16, gsrc + idx * 16);
    }
    CP_COMMIT(); CP_WAIT();
    __syncthreads();

    const int tid = threadIdx.x, lane = tid & 31, w = tid >> 5;
    const int r0 = lane >> 2, il = lane & 3, cb = il * 2;
    const uint32_t offB = (uint32_t)(((lane & 7) + (((lane >> 4) & 1) << 3)) * ST
                                     + (((lane >> 3) & 1) << 3)) * 2;
    const uint32_t uW1a = smb;
    const uint32_t uW1b = smb + TILEB;
    const uint32_t uW2  = smb + 2 * TILEB;
    const uint32_t* gVUp = reinterpret_cast<const uint32_t*>(gVUh);
    const uint32_t* gVVp = reinterpret_cast<const uint32_t*>(gVVh);

    for (int t = blockIdx.x; t < n_tiles; t += gridDim.x) {
        long er0 = (long)t * 256 + w * 16 + r0;
        long er1 = er0 + 8;
        int s0 = __ldg(src + er0), s1 = __ldg(src + er1);
        int d0 = __ldg(dst + er0), d1 = __ldg(dst + er1);
        const uint32_t* pu0 = gVUp + (size_t)s0 * 64;
        const uint32_t* pu1 = gVUp + (size_t)s1 * 64;
        const uint32_t* pv0 = gVVp + (size_t)d0 * 64;
        const uint32_t* pv1 = gVVp + (size_t)d1 * 64;
        const float2* pe0 = reinterpret_cast<const float2*>(E + er0 * 128);
        const float2* pe1 = reinterpret_cast<const float2*>(E + er1 * 128);

        float acc[64];
        #pragma unroll
        for (int i = 0; i < 64; ++i) acc[i] = 0.f;

        // ---- merged GEMM A+B, single-term fp16 ----
        #pragma unroll 1
        for (int ks = 0; ks < 8; ++ks) {
            int i0 = il + 8 * ks, i1 = i0 + 4;
            uint32_t th[4], eh[4];
            {
                float2 u0 = h2tof2(pu0[i0]), u1 = h2tof2(pu1[i0]);
                float2 u2 = h2tof2(pu0[i1]), u3 = h2tof2(pu1[i1]);
                float2 v0 = h2tof2(pv0[i0]), v1 = h2tof2(pv1[i0]);
                float2 v2 = h2tof2(pv0[i1]), v3 = h2tof2(pv1[i1]);
                th[0] = h2_of(fast_tanh(u0.x * v0.x), fast_tanh(u0.y * v0.y));
                th[1] = h2_of(fast_tanh(u1.x * v1.x), fast_tanh(u1.y * v1.y));
                th[2] = h2_of(fast_tanh(u2.x * v2.x), fast_tanh(u2.y * v2.y));
                th[3] = h2_of(fast_tanh(u3.x * v3.x), fast_tanh(u3.y * v3.y));
            }
            {
                float2 e0 = pe0[i0], e1 = pe1[i0], e2 = pe0[i1], e3 = pe1[i1];
                eh[0] = h2_of(lk(e0.x), lk(e0.y));
                eh[1] = h2_of(lk(e1.x), lk(e1.y));
                eh[2] = h2_of(lk(e2.x), lk(e2.y));
                eh[3] = h2_of(lk(e3.x), lk(e3.y));
            }
            const uint32_t bA = uW1a + offB + ks * 32;
            const uint32_t bB = uW1b + offB + ks * 32;
            #pragma unroll
            for (int g = 0; g < 8; ++g) {
                uint32_t go = (uint32_t)g * (16 * ST * 2);
                uint32_t ba[4], bb[4];
                LDSM4(ba, bA + go);
                LDSM4(bb, bB + go);
                mma_f16(acc + 8 * g,     th, ba[0], ba[1]);
                mma_f16(acc + 8 * g + 4, th, ba[2], ba[3]);
                mma_f16(acc + 8 * g,     eh, bb[0], bb[1]);
                mma_f16(acc + 8 * g + 4, eh, bb[2], bb[3]);
            }
        }

        // ---- y1 = relu(acc + b1'): repack into fp16 A-frags for GEMM C ----
        uint32_t yv[8][4];
        #pragma unroll
        for (int ks = 0; ks < 8; ++ks) {
            #pragma unroll
            for (int p = 0; p < 2; ++p) {
                int nf = 2 * ks + p;
                float2 bb = __ldg(reinterpret_cast<const float2*>(gB1p + nf * 8 + cb));
                yv[ks][2*p]   = h2_of(fmaxf(acc[nf*4+0] + bb.x, 0.f),
                                      fmaxf(acc[nf*4+1] + bb.y, 0.f));
                yv[ks][2*p+1] = h2_of(fmaxf(acc[nf*4+2] + bb.x, 0.f),
                                      fmaxf(acc[nf*4+3] + bb.y, 0.f));
            }
        }

        // ---- GEMM C: out = relu(y1 @ W2^T + b2), full n in one pass ----
        float acc2[64];
        #pragma unroll
        for (int i = 0; i < 64; ++i) acc2[i] = 0.f;
        #pragma unroll 1
        for (int ks = 0; ks < 8; ++ks) {
            const uint32_t bC = uW2 + offB + ks * 32;
            #pragma unroll
            for (int g = 0; g < 8; ++g) {
                uint32_t go = (uint32_t)g * (16 * ST * 2);
                uint32_t bc[4];
                LDSM4(bc, bC + go);
                mma_f16(acc2 + 8 * g,     yv[ks], bc[0], bc[1]);
                mma_f16(acc2 + 8 * g + 4, yv[ks], bc[2], bc[3]);
            }
        }
        #pragma unroll
        for (int nf = 0; nf < 16; ++nf) {
            int c = nf * 8 + cb;
            float2 bb = __ldg(reinterpret_cast<const float2*>(b2 + c));
            *reinterpret_cast<float2*>(out + er0 * 128 + c) =
                make_float2(fmaxf(acc2[nf*4+0] + bb.x, 0.f),
                            fmaxf(acc2[nf*4+1] + bb.y, 0.f));
            *reinterpret_cast<float2*>(out + er1 * 128 + c) =
                make_float2(fmaxf(acc2[nf*4+2] + bb.x, 0.f),
                            fmaxf(acc2[nf*4+3] + bb.y, 0.f));
        }
    }
}

// ================= host =================
extern "C" void kernel_launch(void* const* d_in, const int* in_sizes, int n_in,
                              void* d_out, int out_size)
{
    const float* V   = (const float*)d_in[0];
    const float* E   = (const float*)d_in[1];
    const int*   src = (const int*)d_in[2];
    const int*   dst = (const int*)d_in[3];
    const float* U_w = (const float*)d_in[4];
    const float* V_w = (const float*)d_in[5];
    const float* P_w = (const float*)d_in[6];
    const float* P_b = (const float*)d_in[7];
    const float* W1  = (const float*)d_in[8];
    const float* b1  = (const float*)d_in[9];
    const float* W2  = (const float*)d_in[10];
    const float* b2  = (const float*)d_in[11];
    float* out = (float*)d_out;

    int n_nodes = in_sizes[0] / 128;
    int n_edges = in_sizes[2];
    int n_tiles = n_edges / 256;                 // 2500
    int n_ntiles = (n_nodes + 255) / 256;        // 391

    static int sms = 0;
    if (!sms) {
        cudaDeviceGetAttribute(&sms, cudaDevAttrMultiProcessorCount, 0);
        cudaFuncSetAttribute(ecat_node, cudaFuncAttributeMaxDynamicSharedMemorySize, NODE_SMEM);
        cudaFuncSetAttribute(ecat_edge, cudaFuncAttributeMaxDynamicSharedMemorySize, EDGE_SMEM);
    }

    ecat_compose<<<128, 128>>>(W1, P_w, P_b, b1);
    ecat_convert<<<4, PTH>>>(W1, W2, U_w, V_w);
    ecat_node<<<sms, NTH, NODE_SMEM>>>(V, n_nodes, n_ntiles);
    ecat_edge<<<sms, NTH, EDGE_SMEM>>>(E, src, dst, b2, out, n_tiles);
}

// round 17
// speedup vs baseline: 1.4659x; 1.1703x over previous
#include <cuda_runtime.h>
#include <cuda_bf16.h>
#include <cuda_fp16.h>
#include <cstdint>

#define NTH   512                        // edge + node: 16 warps, m=16 per warp
#define PTH   512
#define ST    136                        // elems per weight-tile row (272 B)
#define TILEB (128 * ST * 2)             // 34816 B per 128x128 16-bit tile
#define AST   272                        // bytes per act-tile row (128 fp16 + pad)
#define AWARP (16 * AST)                 // 4352 B per-warp act tile
#define ACT_OFF (3 * TILEB)
#define EDGE_SMEM (3 * TILEB + 16 * AWARP)   // 104448 + 69632 = 174080
#define NODE_SMEM (4 * TILEB)            // U(h,l) V(h,l) bf16 = 139264
#define NODE_PAD 100096

// ---------------- device scratch (static, allowed) ----------------
__device__ __align__(128) __half gVUh[(size_t)NODE_PAD * 128];  // fp16 node projections
__device__ __align__(128) __half gVVh[(size_t)NODE_PAD * 128];
__device__ __align__(16) float gB1p[128];
__device__ __align__(16) char  gWf16[3][TILEB];     // fp16 images: W1a', W1b, W2
__device__ __align__(16) char  gWbf[2][2][TILEB];   // bf16 hi/lo: U_w, V_w (node)

// ---------------- PTX helpers ----------------
__device__ __forceinline__ uint32_t smem_u32(const void* p) {
    uint32_t a;
    asm("{ .reg .u64 t; cvta.to.shared.u64 t, %1; cvt.u32.u64 %0, t; }" : "=r"(a) : "l"(p));
    return a;
}
#define LDSM4(r, addr)                                                              \
    asm volatile("ldmatrix.sync.aligned.m8n8.x4.shared.b16 {%0,%1,%2,%3}, [%4];"    \
                 : "=r"((r)[0]), "=r"((r)[1]), "=r"((r)[2]), "=r"((r)[3])           \
                 : "r"(addr))
#define STS128(addr, v)                                                             \
    asm volatile("st.shared.v4.b32 [%0], {%1,%2,%3,%4};"                            \
                 :: "r"(addr), "r"((v).x), "r"((v).y), "r"((v).z), "r"((v).w) : "memory")
#define STS64(addr, a, b)                                                           \
    asm volatile("st.shared.v2.b32 [%0], {%1,%2};" :: "r"(addr), "r"(a), "r"(b) : "memory")
__device__ __forceinline__ void mma_bf16(float* c, const uint32_t* a, uint32_t b0, uint32_t b1) {
    asm volatile("mma.sync.aligned.m16n8k16.row.col.f32.bf16.bf16.f32 "
                 "{%0,%1,%2,%3}, {%4,%5,%6,%7}, {%8,%9}, {%0,%1,%2,%3};"
                 : "+f"(c[0]), "+f"(c[1]), "+f"(c[2]), "+f"(c[3])
                 : "r"(a[0]), "r"(a[1]), "r"(a[2]), "r"(a[3]), "r"(b0), "r"(b1));
}
__device__ __forceinline__ void mma_f16(float* c, const uint32_t* a, uint32_t b0, uint32_t b1) {
    asm volatile("mma.sync.aligned.m16n8k16.row.col.f32.f16.f16.f32 "
                 "{%0,%1,%2,%3}, {%4,%5,%6,%7}, {%8,%9}, {%0,%1,%2,%3};"
                 : "+f"(c[0]), "+f"(c[1]), "+f"(c[2]), "+f"(c[3])
                 : "r"(a[0]), "r"(a[1]), "r"(a[2]), "r"(a[3]), "r"(b0), "r"(b1));
}
#define CP16(dst, src) \
    asm volatile("cp.async.ca.shared.global [%0], [%1], 16;" :: "r"(dst), "l"(src))
#define CP_COMMIT() asm volatile("cp.async.commit_group;" ::: "memory")
#define CP_WAIT()   asm volatile("cp.async.wait_group 0;" ::: "memory")

// ---------------- numeric helpers ----------------
__device__ __forceinline__ float bf16hi_rn(float a, uint32_t& hbits) {
    uint32_t u = __float_as_uint(a);
    uint32_t r = (u + 0x7FFFu + ((u >> 16) & 1u)) & 0xFFFF0000u;
    hbits = r;
    return __uint_as_float(r);
}
__device__ __forceinline__ uint32_t bf16x2_of(float lo, float hi) {
    uint32_t r;
    asm("cvt.rn.bf16x2.f32 %0, %1, %2;" : "=r"(r) : "f"(hi), "f"(lo));
    return r;
}
__device__ __forceinline__ uint32_t h2_of(float lo, float hi) {
    uint32_t r;
    asm("cvt.rn.f16x2.f32 %0, %1, %2;" : "=r"(r) : "f"(hi), "f"(lo));
    return r;
}
__device__ __forceinline__ float2 h2tof2(uint32_t v) {
    __half2 h = *reinterpret_cast<__half2*>(&v);
    return __half22float2(h);
}
__device__ __forceinline__ void split2(float x, float y, uint32_t& h, uint32_t& l) {
    uint32_t rx, ry;
    float hx = bf16hi_rn(x, rx), hy = bf16hi_rn(y, ry);
    h = __byte_perm(rx, ry, 0x7632);
    l = bf16x2_of(x - hx, y - hy);
}
__device__ __forceinline__ float fast_tanh(float x) {
    float e = __expf(2.f * x);
    return 1.f - __fdividef(2.f, e + 1.f);
}
__device__ __forceinline__ float lk(float v) { return v > 0.f ? v : 0.01f * v; }
// tanh(u*v) on a packed half2 pair
__device__ __forceinline__ uint32_t tanh2mul(uint32_t u, uint32_t v) {
    float2 a = h2tof2(u), b = h2tof2(v);
    return h2_of(fast_tanh(a.x * b.x), fast_tanh(a.y * b.y));
}

// bf16 hi/lo staging (node weights)
__device__ __forceinline__ void stage32(const float* __restrict__ src,
                                        char* Xh, char* Xl, uint32_t off) {
    #pragma unroll
    for (int i = 0; i < 8; ++i) {
        float4 t = reinterpret_cast<const float4*>(src)[i];
        uint32_t r0, r1, r2, r3;
        float h0 = bf16hi_rn(t.x, r0), h1 = bf16hi_rn(t.y, r1);
        float h2 = bf16hi_rn(t.z, r2), h3 = bf16hi_rn(t.w, r3);
        uint2 hh = make_uint2(__byte_perm(r0, r1, 0x7632), __byte_perm(r2, r3, 0x7632));
        uint2 ll = make_uint2(bf16x2_of(t.x - h0, t.y - h1), bf16x2_of(t.z - h2, t.w - h3));
        *reinterpret_cast<uint2*>(Xh + off + i * 8) = hh;
        *reinterpret_cast<uint2*>(Xl + off + i * 8) = ll;
    }
}
// fp16 single staging (edge weights)
__device__ __forceinline__ void stage32h(const float* __restrict__ src,
                                         char* X, uint32_t off) {
    #pragma unroll
    for (int i = 0; i < 8; ++i) {
        float4 t = reinterpret_cast<const float4*>(src)[i];
        uint2 v = make_uint2(h2_of(t.x, t.y), h2_of(t.z, t.w));
        *reinterpret_cast<uint2*>(X + off + i * 8) = v;
    }
}

// bf16 3-term helper for node kernel
__device__ __forceinline__ void mma6(float* acc, const uint32_t* ah, const uint32_t* al,
                                     const uint32_t* bh, const uint32_t* bl) {
    mma_bf16(acc,     ah, bh[0], bh[1]);
    mma_bf16(acc + 4, ah, bh[2], bh[3]);
    mma_bf16(acc,     ah, bl[0], bl[1]);
    mma_bf16(acc + 4, ah, bl[2], bl[3]);
    mma_bf16(acc,     al, bh[0], bh[1]);
    mma_bf16(acc + 4, al, bh[2], bh[3]);
}
__device__ __forceinline__ void gemm_groups(float* acc, const uint32_t* ah, const uint32_t* al,
                                            uint32_t baseH, uint32_t baseL, int ngroups)
{
    #pragma unroll
    for (int g = 0; g < 8; ++g) {
        if (g >= ngroups) break;
        uint32_t bh[4], bl[4];
        LDSM4(bh, baseH + g * (16 * ST * 2));
        LDSM4(bl, baseL + g * (16 * ST * 2));
        mma6(acc + 8 * g, ah, al, bh, bl);
    }
}

// ================= prep 1: W1a' = W1a @ P_w (emit fp16 image 0), b1' =================
__global__ void __launch_bounds__(128, 1)
ecat_compose(const float* __restrict__ W1, const float* __restrict__ P_w,
             const float* __restrict__ P_b, const float* __restrict__ b1)
{
    __shared__ float srow[128];
    int o = blockIdx.x;
    int j = threadIdx.x;
    srow[j] = W1[o * 256 + j];
    __syncthreads();
    float acc = 0.f;
    #pragma unroll 4
    for (int i = 0; i < 128; ++i)
        acc += srow[i] * P_w[i * 128 + j];
    reinterpret_cast<__half*>(gWf16[0])[o * ST + j] = __float2half_rn(acc);
    if (j == 0) {
        float s = 0.f;
        for (int i = 0; i < 128; ++i) s += srow[i] * P_b[i];
        gB1p[o] = b1[o] + s;
    }
}

// ================= prep 2: W1b, W2 -> fp16; U_w, V_w -> bf16 hi/lo =================
__global__ void __launch_bounds__(PTH, 1)
ecat_convert(const float* __restrict__ W1, const float* __restrict__ W2,
             const float* __restrict__ U_w, const float* __restrict__ V_w)
{
    int b = blockIdx.x;
    int tid = threadIdx.x;
    int o = tid >> 2, qo = (tid & 3) * 32;
    uint32_t off = (uint32_t)(o * ST + qo) * 2;
    if (b == 0)      stage32h(W1 + o * 256 + 128 + qo, (char*)gWf16[1], off);
    else if (b == 1) stage32h(W2 + o * 128 + qo, (char*)gWf16[2], off);
    else if (b == 2) stage32(U_w + (size_t)o * 128 + qo, (char*)gWbf[0][0], (char*)gWbf[0][1], off);
    else             stage32(V_w + (size_t)o * 128 + qo, (char*)gWbf[1][0], (char*)gWbf[1][1], off);
}

// ================= prep 3: VU / VV (bf16 3-term compute, fp16 output) =================
__global__ void __launch_bounds__(NTH, 1)
ecat_node(const float* __restrict__ V, int n_nodes, int n_ntiles)
{
    extern __shared__ char sm[];
    uint32_t smb = smem_u32(sm);
    const char* gsrc = &gWbf[0][0][0];
    #pragma unroll
    for (int i = 0; i < 17; ++i) {
        int idx = i * NTH + threadIdx.x;
        CP16(smb + idx * 16, gsrc + idx * 16);   // 17*512 = 8704 chunks exactly
    }
    CP_COMMIT(); CP_WAIT();
    __syncthreads();

    const int tid = threadIdx.x, lane = tid & 31, w = tid >> 5;
    const int r0 = lane >> 2, il = lane & 3;
    const uint32_t offB = (uint32_t)(((lane & 7) + (((lane >> 4) & 1) << 3)) * ST
                                     + (((lane >> 3) & 1) << 3)) * 2;

    for (int t = blockIdx.x; t < n_ntiles; t += gridDim.x) {
        int n0 = t * 256 + w * 16 + r0;
        int n1 = n0 + 8;
        int n0c = n0 < n_nodes ? n0 : 0;
        int n1c = n1 < n_nodes ? n1 : 0;
        const float2* pa0 = reinterpret_cast<const float2*>(V + (size_t)n0c * 128);
        const float2* pa1 = reinterpret_cast<const float2*>(V + (size_t)n1c * 128);

        #pragma unroll 1
        for (int pass = 0; pass < 2; ++pass) {
            uint32_t bH = smb + pass * 2 * TILEB, bL = bH + TILEB;
            float acc[64];
            #pragma unroll
            for (int i = 0; i < 64; ++i) acc[i] = 0.f;
            #pragma unroll 1
            for (int ks = 0; ks < 8; ++ks) {
                int i0 = il + 8 * ks, i1 = i0 + 4;
                float2 a0 = pa0[i0], b0 = pa1[i0], c0 = pa0[i1], d0 = pa1[i1];
                uint32_t ah[4], al[4];
                split2(a0.x, a0.y, ah[0], al[0]);
                split2(b0.x, b0.y, ah[1], al[1]);
                split2(c0.x, c0.y, ah[2], al[2]);
                split2(d0.x, d0.y, ah[3], al[3]);
                gemm_groups(acc, ah, al, bH + offB + ks * 32, bL + offB + ks * 32, 8);
            }
            uint32_t* dstb = reinterpret_cast<uint32_t*>(pass ? gVVh : gVUh);
            #pragma unroll
            for (int nf = 0; nf < 16; ++nf) {
                int cw = nf * 4 + il;     // half2 word index within row
                if (n0 < n_nodes)
                    dstb[(size_t)n0 * 64 + cw] = h2_of(acc[nf*4],   acc[nf*4+1]);
                if (n1 < n_nodes)
                    dstb[(size_t)n1 * 64 + cw] = h2_of(acc[nf*4+2], acc[nf*4+3]);
            }
        }
    }
}

// ========== edge kernel: coalesced act staging + ldmatrix A, fp16 single-term ==========
__global__ void __launch_bounds__(NTH, 1)
ecat_edge(const float* __restrict__ E, const int* __restrict__ src,
          const int* __restrict__ dst, const float* __restrict__ b2,
          float* __restrict__ out, int n_tiles)
{
    extern __shared__ char sm[];
    uint32_t smb = smem_u32(sm);
    const char* gsrc = &gWf16[0][0];
    #pragma unroll
    for (int i = 0; i < 13; ++i) {                 // 3*TILEB/16 = 6528 chunks
        int idx = i * NTH + threadIdx.x;
        if (idx < 3 * TILEB / 16) CP16(smb + idx * 16, gsrc + idx * 16);
    }
    CP_COMMIT(); CP_WAIT();
    __syncthreads();

    const int tid = threadIdx.x, lane = tid & 31, w = tid >> 5;
    const int r0 = lane >> 2, il = lane & 3, cb = il * 2;
    const int r4 = lane >> 3, ch = lane & 7;       // staging: rowgroup, 16B-chunk
    const uint32_t offB = (uint32_t)(((lane & 7) + (((lane >> 4) & 1) << 3)) * ST
                                     + (((lane >> 3) & 1) << 3)) * 2;
    const uint32_t uW1a = smb;
    const uint32_t uW1b = smb + TILEB;
    const uint32_t uW2  = smb + 2 * TILEB;
    const uint32_t uA   = smb + ACT_OFF + (uint32_t)w * AWARP;   // warp-private act tile
    const uint32_t offA = (uint32_t)((lane & 15) * AST + (lane >> 4) * 16);

    for (int t = blockIdx.x; t < n_tiles; t += gridDim.x) {
        long ebase = (long)t * 256 + w * 16;
        __syncwarp();   // prior tile's act-tile reads complete

        // ---- stage tanh(VU[src]*VV[dst]) tile: line-coalesced loads, fp16 STS ----
        #pragma unroll
        for (int rr = 0; rr < 4; ++rr) {
            int row = r4 + rr * 4;
            int si = __ldg(src + ebase + row);
            int di = __ldg(dst + ebase + row);
            const uint4* pu = reinterpret_cast<const uint4*>(gVUh + (size_t)si * 128);
            const uint4* pv = reinterpret_cast<const uint4*>(gVVh + (size_t)di * 128);
            #pragma unroll
            for (int hf = 0; hf < 2; ++hf) {
                uint4 U = pu[hf * 8 + ch];
                uint4 Vv = pv[hf * 8 + ch];
                uint4 R;
                R.x = tanh2mul(U.x, Vv.x);
                R.y = tanh2mul(U.y, Vv.y);
                R.z = tanh2mul(U.z, Vv.z);
                R.w = tanh2mul(U.w, Vv.w);
                STS128(uA + row * AST + hf * 128 + ch * 16, R);
            }
        }
        __syncwarp();

        // ---- GEMM A: acc = tanh_tile @ W1a'^T (A via ldmatrix) ----
        float acc[64];
        #pragma unroll
        for (int i = 0; i < 64; ++i) acc[i] = 0.f;
        #pragma unroll 1
        for (int ks = 0; ks < 8; ++ks) {
            uint32_t ta[4];
            LDSM4(ta, uA + offA + ks * 32);
            const uint32_t bA = uW1a + offB + ks * 32;
            #pragma unroll
            for (int g = 0; g < 8; ++g) {
                uint32_t go = (uint32_t)g * (16 * ST * 2);
                uint32_t ba[4];
                LDSM4(ba, bA + go);
                mma_f16(acc + 8 * g,     ta, ba[0], ba[1]);
                mma_f16(acc + 8 * g + 4, ta, ba[2], ba[3]);
            }
        }
        __syncwarp();   // A-LDSM reads complete before overwrite

        // ---- stage leaky(E) tile: sub-line coalesced fp32 loads, fp16 STS ----
        #pragma unroll
        for (int rr = 0; rr < 4; ++rr) {
            int row = r4 + rr * 4;
            const float4* pe = reinterpret_cast<const float4*>(E + (ebase + row) * 128);
            #pragma unroll
            for (int j = 0; j < 4; ++j) {
                float4 e = pe[j * 8 + ch];                 // bytes j*128 + ch*16
                uint32_t p0 = h2_of(lk(e.x), lk(e.y));
                uint32_t p1 = h2_of(lk(e.z), lk(e.w));
                STS64(uA + row * AST + j * 64 + ch * 8, p0, p1);
            }
        }
        __syncwarp();

        // ---- GEMM B: acc += leakyE_tile @ W1b^T ----
        #pragma unroll 1
        for (int ks = 0; ks < 8; ++ks) {
            uint32_t te[4];
            LDSM4(te, uA + offA + ks * 32);
            const uint32_t bB = uW1b + offB + ks * 32;
            #pragma unroll
            for (int g = 0; g < 8; ++g) {
                uint32_t go = (uint32_t)g * (16 * ST * 2);
                uint32_t bb[4];
                LDSM4(bb, bB + go);
                mma_f16(acc + 8 * g,     te, bb[0], bb[1]);
                mma_f16(acc + 8 * g + 4, te, bb[2], bb[3]);
            }
        }

        // ---- y1 = relu(acc + b1'): repack into fp16 A-frags for GEMM C ----
        uint32_t yv[8][4];
        #pragma unroll
        for (int ks = 0; ks < 8; ++ks) {
            #pragma unroll
            for (int p = 0; p < 2; ++p) {
                int nf = 2 * ks + p;
                float2 bb = __ldg(reinterpret_cast<const float2*>(gB1p + nf * 8 + cb));
                yv[ks][2*p]   = h2_of(fmaxf(acc[nf*4+0] + bb.x, 0.f),
                                      fmaxf(acc[nf*4+1] + bb.y, 0.f));
                yv[ks][2*p+1] = h2_of(fmaxf(acc[nf*4+2] + bb.x, 0.f),
                                      fmaxf(acc[nf*4+3] + bb.y, 0.f));
            }
        }

        // ---- GEMM C: out = relu(y1 @ W2^T + b2), full n in one pass ----
        float acc2[64];
        #pragma unroll
        for (int i = 0; i < 64; ++i) acc2[i] = 0.f;
        #pragma unroll 1
        for (int ks = 0; ks < 8; ++ks) {
            const uint32_t bC = uW2 + offB + ks * 32;
            #pragma unroll
            for (int g = 0; g < 8; ++g) {
                uint32_t go = (uint32_t)g * (16 * ST * 2);
                uint32_t bc[4];
                LDSM4(bc, bC + go);
                mma_f16(acc2 + 8 * g,     yv[ks], bc[0], bc[1]);
                mma_f16(acc2 + 8 * g + 4, yv[ks], bc[2], bc[3]);
            }
        }
        long er0 = ebase + r0;
        long er1 = er0 + 8;
        #pragma unroll
        for (int nf = 0; nf < 16; ++nf) {
            int c = nf * 8 + cb;
            float2 bb = __ldg(reinterpret_cast<const float2*>(b2 + c));
            *reinterpret_cast<float2*>(out + er0 * 128 + c) =
                make_float2(fmaxf(acc2[nf*4+0] + bb.x, 0.f),
                            fmaxf(acc2[nf*4+1] + bb.y, 0.f));
            *reinterpret_cast<float2*>(out + er1 * 128 + c) =
                make_float2(fmaxf(acc2[nf*4+2] + bb.x, 0.f),
                            fmaxf(acc2[nf*4+3] + bb.y, 0.f));
        }
    }
}

// ================= host =================
extern "C" void kernel_launch(void* const* d_in, const int* in_sizes, int n_in,
                              void* d_out, int out_size)
{
    const float* V   = (const float*)d_in[0];
    const float* E   = (const float*)d_in[1];
    const int*   src = (const int*)d_in[2];
    const int*   dst = (const int*)d_in[3];
    const float* U_w = (const float*)d_in[4];
    const float* V_w = (const float*)d_in[5];
    const float* P_w = (const float*)d_in[6];
    const float* P_b = (const float*)d_in[7];
    const float* W1  = (const float*)d_in[8];
    const float* b1  = (const float*)d_in[9];
    const float* W2  = (const float*)d_in[10];
    const float* b2  = (const float*)d_in[11];
    float* out = (float*)d_out;

    int n_nodes = in_sizes[0] / 128;
    int n_edges = in_sizes[2];
    int n_tiles = n_edges / 256;                 // 2500
    int n_ntiles = (n_nodes + 255) / 256;        // 391

    static int sms = 0;
    if (!sms) {
        cudaDeviceGetAttribute(&sms, cudaDevAttrMultiProcessorCount, 0);
        cudaFuncSetAttribute(ecat_node, cudaFuncAttributeMaxDynamicSharedMemorySize, NODE_SMEM);
        cudaFuncSetAttribute(ecat_edge, cudaFuncAttributeMaxDynamicSharedMemorySize, EDGE_SMEM);
    }

    ecat_compose<<<128, 128>>>(W1, P_w, P_b, b1);
    ecat_convert<<<4, PTH>>>(W1, W2, U_w, V_w);
    ecat_node<<<sms, NTH, NODE_SMEM>>>(V, n_nodes, n_ntiles);
    ecat_edge<<<sms, NTH, EDGE_SMEM>>>(E, src, dst, b2, out, n_tiles);
}